// round 5
// baseline (speedup 1.0000x reference)
#include <cuda_runtime.h>
#include <cstdint>

// Problem constants
#define B_TOT  2048
#define S_LEN  256
#define DIN    3
#define HID    128
#define D_OUT  6
#define DT_F   0.1f

// 7 batch rows per CTA, 293 CTAs, 2 CTAs per SM (occupancy experiment: 8 warps/SMSP).
// 512 threads: tp = tid&31 (neuron QUAD n0=4tp..4tp+3), ks = tid>>5 (K-slice: 8 cols).
// Warps uniform in ks -> all h loads warp-uniform broadcasts.
// h stored SPLATTED: hsp[row][2j]=hsp[row][2j+1]=h[j]; LDS.128 -> (hj,hj,hj+1,hj+1)
// feeds neuron-packed f32x2 FMAs directly.
#define ROWS   7
#define NCTA   ((B_TOT + ROWS - 1) / ROWS)   // 293
#define NTHR   512
#define NSL    16                            // K slices
#define CPS    8                             // cols per slice
#define SPC    (2 * HID)                     // splat row pitch: 256 floats

#define XSZ    (ROWS * S_LEN * DIN)          // 5376 floats
#define HSPSZ  (ROWS * SPC)                  // 1792 floats per buffer
#define PARTSZ (NSL * ROWS * HID)            // 14336 floats
#define SMEMF  (XSZ + 2 * HSPSZ + PARTSZ)    // 23296 floats = 93184 B

typedef unsigned long long u64;

// ---- packed f32x2 FMA (SASS FFMA2) ----
__device__ __forceinline__ u64 fma2(u64 a, u64 b, u64 c) {
    u64 d;
    asm("fma.rn.f32x2 %0, %1, %2, %3;" : "=l"(d) : "l"(a), "l"(b), "l"(c));
    return d;
}
__device__ __forceinline__ u64 pk(float lo, float hi) {
    u64 v;
    asm("mov.b64 %0, {%1, %2};" : "=l"(v) : "f"(lo), "f"(hi));
    return v;
}
__device__ __forceinline__ void upk(u64 v, float& lo, float& hi) {
    asm("mov.b64 {%0, %1}, %2;" : "=f"(lo), "=f"(hi) : "l"(v));
}

// Accurate-enough tanh: ex2.approx + fast divide; abs err ~1e-6.
__device__ __forceinline__ float fast_tanh(float x) {
    float ax = fminf(fabsf(x), 15.0f);
    float e  = __expf(2.0f * ax);
    float t  = 1.0f - __fdividef(2.0f, e + 1.0f);
    return copysignf(t, x);
}

// softplus(x) = max(x,0) + log1p(exp(-|x|))  (stable, accurate)
__device__ __forceinline__ float softplus_acc(float x) {
    return fmaxf(x, 0.0f) + log1pf(__expf(-fabsf(x)));
}

extern __shared__ float smem_dyn[];

__global__ void __launch_bounds__(NTHR, 2)
cfc_kernel(const float* __restrict__ x,        // [B, S, 3]
           const float* __restrict__ W_xh,     // [128, 3]
           const float* __restrict__ W_hh,     // [128, 128]
           const float* __restrict__ b_hh,     // [128]
           const float* __restrict__ log_tau,  // [128]
           const float* __restrict__ fc_W,     // [6, 128]
           const float* __restrict__ fc_b,     // [6]
           float* __restrict__ out)            // [B, 6]
{
    float* xsh  = smem_dyn;            // x tile
    float* hsp0 = xsh + XSZ;           // splatted h, buffer 0
    float* hsp1 = hsp0 + HSPSZ;        // splatted h, buffer 1
    float* part = hsp1 + HSPSZ;        // partials [ks][row][neuron]

    const int tid = threadIdx.x;
    const int tp  = tid & 31;            // neuron quad: n0 = 4tp .. 4tp+3
    const int ks  = tid >> 5;            // K-slice: cols [ks*8, ks*8+8)
    const int n0  = 4 * tp;
    const int colb = ks * CPS;
    const int cb  = blockIdx.x * ROWS;   // global batch-row base

    // ---- W_hh neuron-interleaved pairs for this slice: 16 u64 = 32 regs ----
    u64 W01[CPS], W23[CPS];
    {
        const float* w0 = W_hh + (n0 + 0) * HID + colb;
        const float* w1 = W_hh + (n0 + 1) * HID + colb;
        const float* w2 = W_hh + (n0 + 2) * HID + colb;
        const float* w3 = W_hh + (n0 + 3) * HID + colb;
        #pragma unroll
        for (int c = 0; c < CPS; c++) {
            W01[c] = pk(w0[c], w1[c]);
            W23[c] = pk(w2[c], w3[c]);
        }
    }

    // ---- per-quad leak coefficients (used only by finish threads, ks<7) ----
    float aa0 = DT_F / (softplus_acc(log_tau[n0 + 0]) + 0.001f);
    float aa1 = DT_F / (softplus_acc(log_tau[n0 + 1]) + 0.001f);
    float aa2 = DT_F / (softplus_acc(log_tau[n0 + 2]) + 0.001f);
    float aa3 = DT_F / (softplus_acc(log_tau[n0 + 3]) + 0.001f);

    // ---- stage x tile; zero splat-h buffers ----
    {
        const float* src = x + (size_t)cb * (S_LEN * DIN);
        int lim = (B_TOT - cb) * (S_LEN * DIN);
        if (lim > XSZ) lim = XSZ;
        for (int i = tid; i < XSZ; i += NTHR)
            xsh[i] = (i < lim) ? src[i] : 0.0f;
    }
    for (int i = tid; i < 2 * HSPSZ; i += NTHR) hsp0[i] = 0.0f;
    __syncthreads();

    // ================= sequential scan over S =================
    for (int s = 0; s < S_LEN; s++) {
        const float* hcur = (s & 1) ? hsp1 : hsp0;
        float*       hnxt = (s & 1) ? hsp0 : hsp1;
        const float* hb = hcur + colb * 2;

        // ---- row batch A: rows 0..3 (acc live: 8 u64) ----
        {
            u64 a01[4], a23[4];
            #pragma unroll
            for (int r = 0; r < 4; r++) { a01[r] = 0ull; a23[r] = 0ull; }
            #pragma unroll
            for (int c2 = 0; c2 < CPS / 2; c2++) {     // 2 cols per iter
                #pragma unroll
                for (int r = 0; r < 4; r++) {
                    ulonglong2 hv = *reinterpret_cast<const ulonglong2*>(
                        hb + r * SPC + c2 * 4);
                    a01[r] = fma2(W01[2 * c2],     hv.x, a01[r]);
                    a23[r] = fma2(W23[2 * c2],     hv.x, a23[r]);
                    a01[r] = fma2(W01[2 * c2 + 1], hv.y, a01[r]);
                    a23[r] = fma2(W23[2 * c2 + 1], hv.y, a23[r]);
                }
            }
            #pragma unroll
            for (int r = 0; r < 4; r++) {
                ulonglong2 v; v.x = a01[r]; v.y = a23[r];
                *reinterpret_cast<ulonglong2*>(part + (ks * ROWS + r) * HID + n0) = v;
            }
        }
        // ---- row batch B: rows 4..6 (acc live: 6 u64) ----
        {
            u64 a01[3], a23[3];
            #pragma unroll
            for (int r = 0; r < 3; r++) { a01[r] = 0ull; a23[r] = 0ull; }
            #pragma unroll
            for (int c2 = 0; c2 < CPS / 2; c2++) {
                #pragma unroll
                for (int r = 0; r < 3; r++) {
                    ulonglong2 hv = *reinterpret_cast<const ulonglong2*>(
                        hb + (4 + r) * SPC + c2 * 4);
                    a01[r] = fma2(W01[2 * c2],     hv.x, a01[r]);
                    a23[r] = fma2(W23[2 * c2],     hv.x, a23[r]);
                    a01[r] = fma2(W01[2 * c2 + 1], hv.y, a01[r]);
                    a23[r] = fma2(W23[2 * c2 + 1], hv.y, a23[r]);
                }
            }
            #pragma unroll
            for (int r = 0; r < 3; r++) {
                ulonglong2 v; v.x = a01[r]; v.y = a23[r];
                *reinterpret_cast<ulonglong2*>(part + (ks * ROWS + 4 + r) * HID + n0) = v;
            }
        }
        __syncthreads();

        // ---- finish: threads with ks<7 finish quad tp of row ks ----
        if (ks < ROWS) {
            const int row = ks;
            float z0 = 0.f, z1 = 0.f, z2 = 0.f, z3 = 0.f;
            #pragma unroll
            for (int q = 0; q < NSL; q++) {
                ulonglong2 pv = *reinterpret_cast<const ulonglong2*>(
                    part + (q * ROWS + row) * HID + n0);
                float p0, p1, p2, p3;
                upk(pv.x, p0, p1);
                upk(pv.y, p2, p3);
                z0 += p0; z1 += p1; z2 += p2; z3 += p3;
            }
            // x projection params from gmem (L1-resident after step 0)
            const float4* wxa = reinterpret_cast<const float4*>(W_xh);
            float4 wa = wxa[3 * tp + 0];
            float4 wb = wxa[3 * tp + 1];
            float4 wc = wxa[3 * tp + 2];
            float4 b4 = reinterpret_cast<const float4*>(b_hh)[tp];
            const float* xr = xsh + row * (S_LEN * DIN) + s * 3;
            float x0 = xr[0], x1 = xr[1], x2 = xr[2];
            z0 += fmaf(wa.x, x0, fmaf(wa.y, x1, fmaf(wa.z, x2, b4.x)));
            z1 += fmaf(wa.w, x0, fmaf(wb.x, x1, fmaf(wb.y, x2, b4.y)));
            z2 += fmaf(wb.z, x0, fmaf(wb.w, x1, fmaf(wc.x, x2, b4.z)));
            z3 += fmaf(wc.y, x0, fmaf(wc.z, x1, fmaf(wc.w, x2, b4.w)));
            float f0 = fast_tanh(z0), f1 = fast_tanh(z1);
            float f2 = fast_tanh(z2), f3 = fast_tanh(z3);
            // old h from splat buffer
            ulonglong2 hv0 = *reinterpret_cast<const ulonglong2*>(hcur + row * SPC + 8 * tp);
            ulonglong2 hv1 = *reinterpret_cast<const ulonglong2*>(hcur + row * SPC + 8 * tp + 4);
            float h0, h1, h2, h3, junk;
            upk(hv0.x, h0, junk);
            upk(hv0.y, h1, junk);
            upk(hv1.x, h2, junk);
            upk(hv1.y, h3, junk);
            h0 = fmaf(aa0, f0 - h0, h0);
            h1 = fmaf(aa1, f1 - h1, h1);
            h2 = fmaf(aa2, f2 - h2, h2);
            h3 = fmaf(aa3, f3 - h3, h3);
            ulonglong2 o0, o1;
            o0.x = pk(h0, h0); o0.y = pk(h1, h1);
            o1.x = pk(h2, h2); o1.y = pk(h3, h3);
            *reinterpret_cast<ulonglong2*>(hnxt + row * SPC + 8 * tp)     = o0;
            *reinterpret_cast<ulonglong2*>(hnxt + row * SPC + 8 * tp + 4) = o1;
        }
        __syncthreads();
    }

    // ================= output head: softplus(h_T @ fc_W^T + fc_b) =================
    const float* hf = hsp0;   // S_LEN even -> final state in buffer 0 (splatted)
    if (tid < ROWS * D_OUT) {
        const int r = tid / D_OUT;
        const int o = tid % D_OUT;
        const int grow = cb + r;
        if (grow < B_TOT) {
            float z = fc_b[o];
            const float* wrow = fc_W + o * HID;
            const float* hrow = hf + r * SPC;
            #pragma unroll
            for (int j = 0; j < HID; j++)
                z = fmaf(wrow[j], hrow[2 * j], z);
            out[grow * D_OUT + o] = softplus_acc(z);
        }
    }
}

extern "C" void kernel_launch(void* const* d_in, const int* in_sizes, int n_in,
                              void* d_out, int out_size) {
    const float* x       = (const float*)d_in[0];
    const float* W_xh    = (const float*)d_in[1];
    const float* W_hh    = (const float*)d_in[2];
    const float* b_hh    = (const float*)d_in[3];
    const float* log_tau = (const float*)d_in[4];
    const float* fc_W    = (const float*)d_in[5];
    const float* fc_b    = (const float*)d_in[6];
    float* out = (float*)d_out;

    const size_t shmem = (size_t)SMEMF * sizeof(float);  // 93184 B per CTA
    cudaFuncSetAttribute(cfc_kernel, cudaFuncAttributeMaxDynamicSharedMemorySize, (int)shmem);

    cfc_kernel<<<NCTA, NTHR, shmem>>>(x, W_xh, W_hh, b_hh, log_tau, fc_W, fc_b, out);
}